// round 16
// baseline (speedup 1.0000x reference)
#include <cuda_runtime.h>
#include <cuda_fp16.h>
#include <stdint.h>
#include <math.h>

// ---------------- scratch buffers (static device memory, no allocs) ----------
#define NTOK 4096              // 4 * 1024 rows
#define HID  1024
__device__ float g_X1 [NTOK * HID];
__device__ float g_F  [NTOK * HID];
__device__ float g_bqkv[3 * HID];
__device__ __half g_Ah[NTOK * HID];       // activations fp16 (x / O / X1)
__device__ __half g_Hh[NTOK * 4 * HID];   // QKV, later FF hidden
__device__ __half g_Bq[HID * 3 * HID];    // [K=1024][N=3072] Wq|Wk|Wv (natural)
__device__ __half g_Bo[HID * HID];        // [1024][1024]
__device__ __half g_B1[HID * 4 * HID];    // [1024][4096]
__device__ __half g_B2[4 * HID * HID];    // [4096][1024]

// ---------------- PTX helpers (arch-neutral only) -----------------------------
__device__ __forceinline__ uint32_t smem_u32(const void* p) {
    uint32_t a;
    asm("{ .reg .u64 t; cvta.to.shared.u64 t, %1; cvt.u32.u64 %0, t; }"
        : "=r"(a) : "l"(p));
    return a;
}
#define CP_ASYNC16(s, g) \
    asm volatile("cp.async.cg.shared.global [%0], [%1], 16;" :: "r"(s), "l"(g))
#define CP_COMMIT() asm volatile("cp.async.commit_group;" ::: "memory")
#define CP_WAIT(n)  asm volatile("cp.async.wait_group %0;" :: "n"(n) : "memory")
#define LDSM_X4(r, addr) \
    asm volatile("ldmatrix.sync.aligned.m8n8.x4.shared.b16 {%0,%1,%2,%3}, [%4];" \
        : "=r"((r)[0]), "=r"((r)[1]), "=r"((r)[2]), "=r"((r)[3]) : "r"(addr))
#define LDSM_X2(r, addr) \
    asm volatile("ldmatrix.sync.aligned.m8n8.x2.shared.b16 {%0,%1}, [%2];" \
        : "=r"((r)[0]), "=r"((r)[1]) : "r"(addr))
#define LDSM_X2T(r, addr) \
    asm volatile("ldmatrix.sync.aligned.m8n8.x2.trans.shared.b16 {%0,%1}, [%2];" \
        : "=r"((r)[0]), "=r"((r)[1]) : "r"(addr))
#define MMAF16(c, a, b0, b1) \
    asm volatile("mma.sync.aligned.m16n8k16.row.col.f32.f16.f16.f32 " \
        "{%0,%1,%2,%3}, {%4,%5,%6,%7}, {%8,%9}, {%0,%1,%2,%3};" \
        : "+f"((c)[0]), "+f"((c)[1]), "+f"((c)[2]), "+f"((c)[3]) \
        : "r"((a)[0]), "r"((a)[1]), "r"((a)[2]), "r"((a)[3]), "r"(b0), "r"(b1))

__device__ __forceinline__ uint32_t pack_h2f(float x, float y) {
    __half2 p = __halves2half2(__float2half_rn(x), __float2half_rn(y));
    return *reinterpret_cast<uint32_t*>(&p);
}
__device__ __forceinline__ uint2 cvt4(float4 v) {
    uint2 o;
    o.x = pack_h2f(v.x, v.y);
    o.y = pack_h2f(v.z, v.w);
    return o;
}

// ---------------- conversion kernels -----------------------------------------
// fp32 -> fp16 (x)
__global__ __launch_bounds__(256) void cvt_kernel(
    const float* __restrict__ A, __half* __restrict__ H, int n4)
{
    int i = blockIdx.x * 256 + threadIdx.x;
    if (i >= n4) return;
    ((uint2*)H)[i] = cvt4(((const float4*)A)[i]);
}

// streaming prep: all weights fp32 -> fp16 in natural [K][N] layout, + bias pack
__global__ __launch_bounds__(256) void prep_kernel(
    const float* __restrict__ Wq, const float* __restrict__ Wk,
    const float* __restrict__ Wv, const float* __restrict__ Wo,
    const float* __restrict__ W1, const float* __restrict__ W2,
    const float* __restrict__ bq, const float* __restrict__ bk,
    const float* __restrict__ bv,
    __half* __restrict__ Hq, __half* __restrict__ Ho,
    __half* __restrict__ H1, __half* __restrict__ H2,
    float* __restrict__ bqkv)
{
    int i = blockIdx.x * 256 + threadIdx.x;
    if (i < 786432) {                       // Wq|Wk|Wv -> Hq [1024][3072]
        int z = i >> 18, rem = i & 262143;
        const float* W = (z == 0) ? Wq : (z == 1) ? Wk : Wv;
        int k = rem >> 8, n4 = rem & 255;
        uint2 o = cvt4(((const float4*)W)[rem]);
        *(uint2*)(Hq + (size_t)k * 3072 + z * 1024 + n4 * 4) = o;
    } else if (i < 1048576) {               // Wo
        int rem = i - 786432;
        ((uint2*)Ho)[rem] = cvt4(((const float4*)Wo)[rem]);
    } else if (i < 2097152) {               // W1
        int rem = i - 1048576;
        ((uint2*)H1)[rem] = cvt4(((const float4*)W1)[rem]);
    } else if (i < 3145728) {               // W2
        int rem = i - 2097152;
        ((uint2*)H2)[rem] = cvt4(((const float4*)W2)[rem]);
    } else if (i < 3146496) {               // bias pack (768 f4)
        int rem = i - 3145728;
        int z = rem >> 8, j = rem & 255;
        const float* b = (z == 0) ? bq : (z == 1) ? bk : bv;
        ((float4*)bqkv)[z * 256 + j] = ((const float4*)b)[j];
    }
}

// ---------------- single-fp16 tensor-core GEMM (trans-B, 3-stage) ------------
#define G_PART  8192
#define G_STAGE (2 * G_PART)
#define G_SMEM  (3 * G_STAGE)

__global__ __launch_bounds__(256) void gemm_tc_kernel(
    const __half* __restrict__ Ah, const __half* __restrict__ Bh,
    const float* __restrict__ bias,
    float* __restrict__ Cf, __half* __restrict__ Ch,
    int M, int N, int K, int act)
{
    extern __shared__ char smem[];
    const uint32_t sb = smem_u32(smem);
    const int tid = threadIdx.x;
    const int wid = tid >> 5, lane = tid & 31;
    const int warp_m = wid >> 2, warp_n = wid & 3;
    const int bm = blockIdx.y * 128, bn = blockIdx.x * 128;

    float acc[4][4][4];
    #pragma unroll
    for (int i = 0; i < 4; ++i)
        #pragma unroll
        for (int j = 0; j < 4; ++j)
            #pragma unroll
            for (int r = 0; r < 4; ++r) acc[i][j][r] = 0.f;

    const int swz = (lane & 7) >> 1;
    const int rA = warp_m * 64 + ((lane >> 3) & 1) * 8 + (lane & 7);
    const int kA = lane >> 4;
    const int kB16 = lane & 15;

    const int nst = K >> 5;

    auto load_stage = [&](int j, int slot) {
        const uint32_t st = sb + (uint32_t)slot * G_STAGE;
        const int kc = j * 32;
        #pragma unroll
        for (int t = 0; t < 2; ++t) {
            int idx = tid + t * 256;
            int row = idx >> 2, ch = idx & 3;
            uint32_t so = (uint32_t)row * 64 + (uint32_t)((ch ^ ((row >> 1) & 3)) << 4);
            CP_ASYNC16(st + so, Ah + (size_t)(bm + row) * K + kc + ch * 8);
        }
        #pragma unroll
        for (int t = 0; t < 2; ++t) {
            int idx = tid + t * 256;
            int row = idx >> 4, c = idx & 15;
            uint32_t so = (uint32_t)row * 256 + (uint32_t)((c ^ (row & 15)) << 4);
            CP_ASYNC16(st + G_PART + so, Bh + (size_t)(kc + row) * N + bn + c * 8);
        }
        CP_COMMIT();
    };

    load_stage(0, 0);
    load_stage(1, 1);

    int slot = 0, slot2 = 2;
    for (int j = 0; j < nst; ++j) {
        if (j + 1 < nst) { CP_WAIT(1); }
        else             { CP_WAIT(0); }
        __syncthreads();
        if (j + 2 < nst) load_stage(j + 2, slot2);

        const uint32_t st = sb + (uint32_t)slot * G_STAGE;
        #pragma unroll
        for (int ks = 0; ks < 2; ++ks) {
            uint32_t ah[4][4], bh[4][2];
            #pragma unroll
            for (int mt = 0; mt < 4; ++mt) {
                uint32_t ao = (uint32_t)(rA + mt * 16) * 64
                            + (uint32_t)(((ks * 2 + kA) ^ swz) << 4);
                LDSM_X4(ah[mt], st + ao);
            }
            {
                int krow = ks * 16 + kB16;
                uint32_t brow = st + G_PART + (uint32_t)krow * 256;
                #pragma unroll
                for (int nf = 0; nf < 4; ++nf) {
                    uint32_t chunk = (uint32_t)((warp_n * 4 + nf) ^ (krow & 15));
                    LDSM_X2T(bh[nf], brow + (chunk << 4));
                }
            }
            #pragma unroll
            for (int mt = 0; mt < 4; ++mt)
                #pragma unroll
                for (int nt = 0; nt < 4; ++nt)
                    MMAF16(acc[mt][nt], ah[mt], bh[nt][0], bh[nt][1]);
        }
        slot  = (slot  == 2) ? 0 : slot  + 1;
        slot2 = (slot2 == 2) ? 0 : slot2 + 1;
    }

    // epilogue
    #pragma unroll
    for (int mt = 0; mt < 4; ++mt)
        #pragma unroll
        for (int nt = 0; nt < 4; ++nt) {
            int row0 = bm + warp_m * 64 + mt * 16 + (lane >> 2);
            int col  = bn + warp_n * 32 + nt * 8 + (lane & 3) * 2;
            float b0 = bias[col], b1 = bias[col + 1];
            float v[4];
            v[0] = acc[mt][nt][0] + b0;
            v[1] = acc[mt][nt][1] + b1;
            v[2] = acc[mt][nt][2] + b0;
            v[3] = acc[mt][nt][3] + b1;
            if (act) {
                #pragma unroll
                for (int r = 0; r < 4; ++r)
                    v[r] = 0.5f * v[r] * (1.f + erff(v[r] * 0.70710678118654752f));
            }
            if (Cf) {
                *(float2*)&Cf[(size_t)row0 * N + col]       = make_float2(v[0], v[1]);
                *(float2*)&Cf[(size_t)(row0 + 8) * N + col] = make_float2(v[2], v[3]);
            } else {
                uint32_t p0 = pack_h2f(v[0], v[1]);
                uint32_t p1 = pack_h2f(v[2], v[3]);
                *(uint32_t*)&Ch[(size_t)row0 * N + col]       = p0;
                *(uint32_t*)&Ch[(size_t)(row0 + 8) * N + col] = p1;
            }
        }
}

// ---------------- tensor-core attention (256 thr, 2 heads/warp, 2 CTA/SM) -----
// QKV packed fp16 [4096][3072]. grid (a=64, n=4), 8 warps, warp w = heads
// {2w, 2w+1}. Single KV buffer (K at 0, V at 32K) with split prefetch:
// K(ap+1) issued after syncB (K region dead), V(ap+1) after syncD (V dead).
#define SCW(hh, b, p) ((hh) * 290 + (b) * 18 + (p))
#define ATTN_SMEM (65536 + (290 * 16 + 288) * 4)   // 85248 B -> 2 CTAs/SM

__global__ __launch_bounds__(256, 2) void attn_kernel(
    const __half* __restrict__ Ph, __half* __restrict__ Oh)
{
    extern __shared__ char smem[];
    const uint32_t sb = smem_u32(smem);
    float* sc   = (float*)(smem + 65536);
    float* invb = sc + 290 * 16;

    const int tid = threadIdx.x, lane = tid & 31, w = tid >> 5;
    const int a = blockIdx.x, n = blockIdx.y;
    const int lr = lane >> 2, lc = lane & 3;

    // ---- stage Q into K region, extract fragments for both heads ----
    {
        #pragma unroll
        for (int t = 0; t < 8; ++t) {
            int f = tid + t * 256;
            int hh = f >> 7, bp = (f >> 3) & 15, c = f & 7;
            uint32_t dst = (uint32_t)hh * 2048 + bp * 128 + ((c ^ (bp & 7)) << 4);
            size_t src = (size_t)(n * 1024 + hh * 64 + a) * 3072 + bp * 64 + c * 8;
            CP_ASYNC16(sb + dst, Ph + src);
        }
        CP_COMMIT(); CP_WAIT(0); __syncthreads();
    }
    uint32_t qh[2][4][4];
    {
        int b = lane & 15, cs = lane >> 4;
        #pragma unroll
        for (int e = 0; e < 2; ++e) {
            int h = 2 * w + e;
            #pragma unroll
            for (int ks = 0; ks < 4; ++ks) {
                uint32_t ad = (uint32_t)h * 2048 + b * 128
                            + (((ks * 2 + cs) ^ (b & 7)) << 4);
                LDSM_X4(qh[e][ks], sb + ad);
            }
        }
    }
    __syncthreads();   // Q reads done before K(0) overwrites

    auto stageK = [&](int ap) {
        #pragma unroll
        for (int t = 0; t < 8; ++t) {
            int f = tid + t * 256;
            int hh = f >> 7, bp = (f >> 3) & 15, c = f & 7;
            uint32_t dst = (uint32_t)hh * 2048 + bp * 128 + ((c ^ (bp & 7)) << 4);
            size_t row = (size_t)(n * 1024 + hh * 64 + ap) * 3072;
            CP_ASYNC16(sb + dst, Ph + row + 1024 + bp * 64 + c * 8);
        }
        CP_COMMIT();
    };
    auto stageV = [&](int ap) {
        #pragma unroll
        for (int t = 0; t < 8; ++t) {
            int f = tid + t * 256;
            int hh = f >> 7, bp = (f >> 3) & 15, c = f & 7;
            uint32_t dst = 32768 + (uint32_t)hh * 2048 + bp * 128 + ((c ^ (bp & 7)) << 4);
            size_t row = (size_t)(n * 1024 + hh * 64 + ap) * 3072;
            CP_ASYNC16(sb + dst, Ph + row + 2048 + bp * 64 + c * 8);
        }
        CP_COMMIT();
    };

    float o[2][8][4];
    #pragma unroll
    for (int e = 0; e < 2; ++e)
        #pragma unroll
        for (int nt = 0; nt < 8; ++nt)
            #pragma unroll
            for (int r = 0; r < 4; ++r) o[e][nt][r] = 0.f;

    stageK(0); stageV(0);
    CP_WAIT(0); __syncthreads();

    for (int ap = 0; ap < 64; ++ap) {
        // ---- scores for both heads: S = Q K^T ----
        #pragma unroll
        for (int e = 0; e < 2; ++e) {
            const int h = 2 * w + e;
            float sv[2][4];
            #pragma unroll
            for (int nt = 0; nt < 2; ++nt)
                #pragma unroll
                for (int r = 0; r < 4; ++r) sv[nt][r] = 0.f;
            int bpr = lane & 7, khalf = (lane >> 3) & 1;
            #pragma unroll
            for (int ks = 0; ks < 4; ++ks)
                #pragma unroll
                for (int nt = 0; nt < 2; ++nt) {
                    int row = nt * 8 + bpr;
                    uint32_t ad = (uint32_t)h * 2048 + row * 128
                                + (((ks * 2 + khalf) ^ (row & 7)) << 4);
                    uint32_t k2[2];
                    LDSM_X2(k2, sb + ad);
                    MMAF16(sv[nt], qh[e][ks], k2[0], k2[1]);
                }
            #pragma unroll
            for (int nt = 0; nt < 2; ++nt) {
                int c0 = nt * 8 + 2 * lc;
                sc[SCW(h, lr,     c0)]     = sv[nt][0] * 0.03125f;
                sc[SCW(h, lr,     c0 + 1)] = sv[nt][1] * 0.03125f;
                sc[SCW(h, lr + 8, c0)]     = sv[nt][2] * 0.03125f;
                sc[SCW(h, lr + 8, c0 + 1)] = sv[nt][3] * 0.03125f;
            }
        }
        __syncthreads();   // syncB: scores in sc; K region dead

        if (ap + 1 < 64) stageK(ap + 1);   // prefetch into dead K region

        // ---- 1-pass head-softmax (all 256 threads; one (b,b') each) ----
        {
            const int pb = tid >> 4, pbp = tid & 15;
            float ssum = 0.f;
            #pragma unroll
            for (int hh = 0; hh < 16; ++hh) {
                float e = __expf(sc[SCW(hh, pb, pbp)]);
                ssum += e;
                sc[SCW(hh, pb, pbp)] = e;
            }
            invb[pb * 18 + pbp] = 1.f / ssum;
        }
        __syncthreads();   // syncC

        // ---- AV for both heads: O += (e*inv) V ----
        #pragma unroll
        for (int e = 0; e < 2; ++e) {
            const int h = 2 * w + e;
            uint32_t awh[4];
            {
                float i00 = invb[lr * 18 + 2 * lc],       i01 = invb[lr * 18 + 2 * lc + 1];
                float i10 = invb[(lr + 8) * 18 + 2 * lc], i11 = invb[(lr + 8) * 18 + 2 * lc + 1];
                float i02 = invb[lr * 18 + 2 * lc + 8],       i03 = invb[lr * 18 + 2 * lc + 9];
                float i12 = invb[(lr + 8) * 18 + 2 * lc + 8], i13 = invb[(lr + 8) * 18 + 2 * lc + 9];
                awh[0] = pack_h2f(sc[SCW(h, lr,     2 * lc)] * i00,
                                  sc[SCW(h, lr,     2 * lc + 1)] * i01);
                awh[1] = pack_h2f(sc[SCW(h, lr + 8, 2 * lc)] * i10,
                                  sc[SCW(h, lr + 8, 2 * lc + 1)] * i11);
                awh[2] = pack_h2f(sc[SCW(h, lr,     2 * lc + 8)] * i02,
                                  sc[SCW(h, lr,     2 * lc + 9)] * i03);
                awh[3] = pack_h2f(sc[SCW(h, lr + 8, 2 * lc + 8)] * i12,
                                  sc[SCW(h, lr + 8, 2 * lc + 9)] * i13);
            }
            int bp = lane & 15;
            #pragma unroll
            for (int nt = 0; nt < 8; ++nt) {
                uint32_t ad = 32768 + (uint32_t)h * 2048 + bp * 128
                            + ((nt ^ (bp & 7)) << 4);
                uint32_t v2[2];
                LDSM_X2T(v2, sb + ad);
                MMAF16(o[e][nt], awh, v2[0], v2[1]);
            }
        }
        __syncthreads();   // syncD: V reads + sc reads done

        if (ap + 1 < 64) stageV(ap + 1);   // prefetch into dead V region
        CP_WAIT(0);
        __syncthreads();   // syncA: K(ap+1) + V(ap+1) visible to all
    }

    // ---- write O (one 1024-col row per head) as fp16 ----
    #pragma unroll
    for (int e = 0; e < 2; ++e) {
        const int h = 2 * w + e;
        const size_t orow = (size_t)(n * 1024 + h * 64 + a) * 1024;
        #pragma unroll
        for (int nt = 0; nt < 8; ++nt) {
            int c0 = nt * 8 + 2 * lc;
            uint32_t p0 = pack_h2f(o[e][nt][0], o[e][nt][1]);
            uint32_t p1 = pack_h2f(o[e][nt][2], o[e][nt][3]);
            *(uint32_t*)(Oh + orow + lr * 64 + c0)       = p0;
            *(uint32_t*)(Oh + orow + (lr + 8) * 64 + c0) = p1;
        }
    }
}

// ---------------- fused residual + LayerNorm (+ optional fp16 emit) ----------
__global__ __launch_bounds__(256) void ln_kernel(
    const float* __restrict__ A, const float* __restrict__ R,
    const float* __restrict__ g, const float* __restrict__ bta,
    float* __restrict__ out, __half* __restrict__ Xh)
{
    __shared__ float red[16];
    const int row = blockIdx.x;
    const int tid = threadIdx.x;

    float4 v = ((const float4*)(A + (size_t)row * 1024))[tid];
    float4 r = ((const float4*)(R + (size_t)row * 1024))[tid];
    v.x += r.x; v.y += r.y; v.z += r.z; v.w += r.w;

    float s  = v.x + v.y + v.z + v.w;
    float sq = v.x * v.x + v.y * v.y + v.z * v.z + v.w * v.w;
    #pragma unroll
    for (int o = 16; o > 0; o >>= 1) {
        s  += __shfl_xor_sync(0xffffffffu, s,  o);
        sq += __shfl_xor_sync(0xffffffffu, sq, o);
    }
    if ((tid & 31) == 0) { red[tid >> 5] = s; red[8 + (tid >> 5)] = sq; }
    __syncthreads();
    float S = 0.f, SQ = 0.f;
    #pragma unroll
    for (int w = 0; w < 8; ++w) { S += red[w]; SQ += red[8 + w]; }

    const float mean = S * (1.f / 1024.f);
    const float var  = SQ * (1.f / 1024.f) - mean * mean;
    const float rstd = rsqrtf(var + 1e-5f);

    float4 gv = ((const float4*)g)[tid];
    float4 bv = ((const float4*)bta)[tid];
    float4 o;
    o.x = (v.x - mean) * rstd * gv.x + bv.x;
    o.y = (v.y - mean) * rstd * gv.y + bv.y;
    o.z = (v.z - mean) * rstd * gv.z + bv.z;
    o.w = (v.w - mean) * rstd * gv.w + bv.w;
    ((float4*)(out + (size_t)row * 1024))[tid] = o;

    if (Xh) {
        size_t oo = (size_t)row * 1024 + tid * 4;
        *(__half2*)(Xh + oo)     = __halves2half2(__float2half_rn(o.x), __float2half_rn(o.y));
        *(__half2*)(Xh + oo + 2) = __halves2half2(__float2half_rn(o.z), __float2half_rn(o.w));
    }
}

// ---------------- launch ------------------------------------------------------
extern "C" void kernel_launch(void* const* d_in, const int* in_sizes, int n_in,
                              void* d_out, int out_size)
{
    const float* x  = (const float*)d_in[0];
    const float* Wq = (const float*)d_in[1];
    const float* bq = (const float*)d_in[2];
    const float* Wk = (const float*)d_in[3];
    const float* bk = (const float*)d_in[4];
    const float* Wv = (const float*)d_in[5];
    const float* bv = (const float*)d_in[6];
    const float* Wo = (const float*)d_in[7];
    const float* bo = (const float*)d_in[8];
    const float* g1 = (const float*)d_in[9];
    const float* b1 = (const float*)d_in[10];
    const float* W1 = (const float*)d_in[11];
    const float* c1 = (const float*)d_in[12];
    const float* W2 = (const float*)d_in[13];
    const float* c2 = (const float*)d_in[14];
    const float* g2 = (const float*)d_in[15];
    const float* b2 = (const float*)d_in[16];
    float* out = (float*)d_out;

    float *pX1, *pF, *pbqkv;
    __half *pAh, *pHh, *pBq, *pBo, *pB1, *pB2;
    cudaGetSymbolAddress((void**)&pX1,  g_X1);
    cudaGetSymbolAddress((void**)&pF,   g_F);
    cudaGetSymbolAddress((void**)&pbqkv,g_bqkv);
    cudaGetSymbolAddress((void**)&pAh,  g_Ah);
    cudaGetSymbolAddress((void**)&pHh,  g_Hh);
    cudaGetSymbolAddress((void**)&pBq,  g_Bq);
    cudaGetSymbolAddress((void**)&pBo,  g_Bo);
    cudaGetSymbolAddress((void**)&pB1,  g_B1);
    cudaGetSymbolAddress((void**)&pB2,  g_B2);

    cudaFuncSetAttribute(attn_kernel, cudaFuncAttributeMaxDynamicSharedMemorySize, ATTN_SMEM);
    cudaFuncSetAttribute(gemm_tc_kernel, cudaFuncAttributeMaxDynamicSharedMemorySize, G_SMEM);

    dim3 blk(256);
    const int n4_1 = NTOK * HID / 4;
    dim3 gs1((n4_1 + 255) / 256);
    dim3 ggqkv(3 * HID / 128, NTOK / 128);
    dim3 gg1(HID / 128, NTOK / 128);
    dim3 gg4(4 * HID / 128, NTOK / 128);

    // ---- conversions: x + all weights (streaming, no transpose) ----
    cvt_kernel<<<gs1, blk>>>(x, pAh, n4_1);
    prep_kernel<<<(3146496 + 255) / 256, blk>>>(Wq, Wk, Wv, Wo, W1, W2,
                                                bq, bk, bv,
                                                pBq, pBo, pB1, pB2, pbqkv);

    // ---- QKV GEMM (N=3072) -> fp16 ----
    gemm_tc_kernel<<<ggqkv, blk, G_SMEM>>>(pAh, pBq, pbqkv,
                                           nullptr, pHh,
                                           NTOK, 3 * HID, HID, 0);

    // ---- tensor-core attention (2 CTAs/SM); emits O fp16 ----
    attn_kernel<<<dim3(64, 4), 256, ATTN_SMEM>>>(pHh, pAh);

    // ---- output projection, residual + LN1 (emits X1 fp32 + fp16) ----
    gemm_tc_kernel<<<gg1, blk, G_SMEM>>>(pAh, pBo, bo,
                                         pF, nullptr,
                                         NTOK, HID, HID, 0);
    ln_kernel<<<NTOK, blk>>>(pF, x, g1, b1, pX1, pAh);

    // ---- FFN ----
    gemm_tc_kernel<<<gg4, blk, G_SMEM>>>(pAh, pB1, c1,
                                         nullptr, pHh,
                                         NTOK, 4 * HID, HID, 1);
    gemm_tc_kernel<<<gg1, blk, G_SMEM>>>(pHh, pB2, c2,
                                         pF, nullptr,
                                         NTOK, HID, 4 * HID, 0);

    // ---- residual + LN2 -> output ----
    ln_kernel<<<NTOK, blk>>>(pF, pX1, g2, b2, out, nullptr);
}

// round 17
// speedup vs baseline: 1.0219x; 1.0219x over previous
#include <cuda_runtime.h>
#include <cuda_fp16.h>
#include <stdint.h>
#include <math.h>

// ---------------- scratch buffers (static device memory, no allocs) ----------
#define NTOK 4096              // 4 * 1024 rows
#define HID  1024
__device__ float g_X1 [NTOK * HID];
__device__ float g_F  [NTOK * HID];
__device__ float g_bqkv[3 * HID];
__device__ __half g_Ah[NTOK * HID];       // activations fp16 (x / O / X1)
__device__ __half g_Hh[NTOK * 4 * HID];   // QKV, later FF hidden
__device__ __half g_Bq[HID * 3 * HID];    // [K=1024][N=3072] Wq|Wk|Wv (natural)
__device__ __half g_Bo[HID * HID];        // [1024][1024]
__device__ __half g_B1[HID * 4 * HID];    // [1024][4096]
__device__ __half g_B2[4 * HID * HID];    // [4096][1024]

// ---------------- PTX helpers (arch-neutral only) -----------------------------
__device__ __forceinline__ uint32_t smem_u32(const void* p) {
    uint32_t a;
    asm("{ .reg .u64 t; cvta.to.shared.u64 t, %1; cvt.u32.u64 %0, t; }"
        : "=r"(a) : "l"(p));
    return a;
}
#define CP_ASYNC16(s, g) \
    asm volatile("cp.async.cg.shared.global [%0], [%1], 16;" :: "r"(s), "l"(g))
#define CP_COMMIT() asm volatile("cp.async.commit_group;" ::: "memory")
#define CP_WAIT(n)  asm volatile("cp.async.wait_group %0;" :: "n"(n) : "memory")
#define LDSM_X4(r, addr) \
    asm volatile("ldmatrix.sync.aligned.m8n8.x4.shared.b16 {%0,%1,%2,%3}, [%4];" \
        : "=r"((r)[0]), "=r"((r)[1]), "=r"((r)[2]), "=r"((r)[3]) : "r"(addr))
#define LDSM_X4T(r, addr) \
    asm volatile("ldmatrix.sync.aligned.m8n8.x4.trans.shared.b16 {%0,%1,%2,%3}, [%4];" \
        : "=r"((r)[0]), "=r"((r)[1]), "=r"((r)[2]), "=r"((r)[3]) : "r"(addr))
#define MMAF16(c, a, b0, b1) \
    asm volatile("mma.sync.aligned.m16n8k16.row.col.f32.f16.f16.f32 " \
        "{%0,%1,%2,%3}, {%4,%5,%6,%7}, {%8,%9}, {%0,%1,%2,%3};" \
        : "+f"((c)[0]), "+f"((c)[1]), "+f"((c)[2]), "+f"((c)[3]) \
        : "r"((a)[0]), "r"((a)[1]), "r"((a)[2]), "r"((a)[3]), "r"(b0), "r"(b1))

__device__ __forceinline__ uint32_t pack_h2f(float x, float y) {
    __half2 p = __halves2half2(__float2half_rn(x), __float2half_rn(y));
    return *reinterpret_cast<uint32_t*>(&p);
}
__device__ __forceinline__ uint2 cvt4(float4 v) {
    uint2 o;
    o.x = pack_h2f(v.x, v.y);
    o.y = pack_h2f(v.z, v.w);
    return o;
}

// ---------------- conversion kernels -----------------------------------------
// fp32 -> fp16 (x)
__global__ __launch_bounds__(256) void cvt_kernel(
    const float* __restrict__ A, __half* __restrict__ H, int n4)
{
    int i = blockIdx.x * 256 + threadIdx.x;
    if (i >= n4) return;
    ((uint2*)H)[i] = cvt4(((const float4*)A)[i]);
}

// streaming prep: all weights fp32 -> fp16 in natural [K][N] layout, + bias pack
__global__ __launch_bounds__(256) void prep_kernel(
    const float* __restrict__ Wq, const float* __restrict__ Wk,
    const float* __restrict__ Wv, const float* __restrict__ Wo,
    const float* __restrict__ W1, const float* __restrict__ W2,
    const float* __restrict__ bq, const float* __restrict__ bk,
    const float* __restrict__ bv,
    __half* __restrict__ Hq, __half* __restrict__ Ho,
    __half* __restrict__ H1, __half* __restrict__ H2,
    float* __restrict__ bqkv)
{
    int i = blockIdx.x * 256 + threadIdx.x;
    if (i < 786432) {                       // Wq|Wk|Wv -> Hq [1024][3072]
        int z = i >> 18, rem = i & 262143;
        const float* W = (z == 0) ? Wq : (z == 1) ? Wk : Wv;
        int k = rem >> 8, n4 = rem & 255;
        uint2 o = cvt4(((const float4*)W)[rem]);
        *(uint2*)(Hq + (size_t)k * 3072 + z * 1024 + n4 * 4) = o;
    } else if (i < 1048576) {               // Wo
        int rem = i - 786432;
        ((uint2*)Ho)[rem] = cvt4(((const float4*)Wo)[rem]);
    } else if (i < 2097152) {               // W1
        int rem = i - 1048576;
        ((uint2*)H1)[rem] = cvt4(((const float4*)W1)[rem]);
    } else if (i < 3145728) {               // W2
        int rem = i - 2097152;
        ((uint2*)H2)[rem] = cvt4(((const float4*)W2)[rem]);
    } else if (i < 3146496) {               // bias pack (768 f4)
        int rem = i - 3145728;
        int z = rem >> 8, j = rem & 255;
        const float* b = (z == 0) ? bq : (z == 1) ? bk : bv;
        ((float4*)bqkv)[z * 256 + j] = ((const float4*)b)[j];
    }
}

// ---------------- single-fp16 tensor-core GEMM (trans-B, x4 loads) -----------
// C = act(A @ B + bias); A [M,K] fp16 row-major, B [K,N] fp16 row-major.
#define G_PART  8192
#define G_STAGE (2 * G_PART)
#define G_SMEM  (3 * G_STAGE)

__global__ __launch_bounds__(256) void gemm_tc_kernel(
    const __half* __restrict__ Ah, const __half* __restrict__ Bh,
    const float* __restrict__ bias,
    float* __restrict__ Cf, __half* __restrict__ Ch,
    int M, int N, int K, int act)
{
    extern __shared__ char smem[];
    const uint32_t sb = smem_u32(smem);
    const int tid = threadIdx.x;
    const int wid = tid >> 5, lane = tid & 31;
    const int warp_m = wid >> 2, warp_n = wid & 3;
    const int bm = blockIdx.y * 128, bn = blockIdx.x * 128;

    float acc[4][4][4];
    #pragma unroll
    for (int i = 0; i < 4; ++i)
        #pragma unroll
        for (int j = 0; j < 4; ++j)
            #pragma unroll
            for (int r = 0; r < 4; ++r) acc[i][j][r] = 0.f;

    const int swz = (lane & 7) >> 1;
    const int rA = warp_m * 64 + ((lane >> 3) & 1) * 8 + (lane & 7);
    const int kA = lane >> 4;
    const int kB16 = lane & 15;     // k-row within 16 (valid for all 32 lanes)
    const int nfh  = lane >> 4;     // 0 for lanes 0-15 (m0,m1), 1 for 16-31 (m2,m3)

    const int nst = K >> 5;

    auto load_stage = [&](int j, int slot) {
        const uint32_t st = sb + (uint32_t)slot * G_STAGE;
        const int kc = j * 32;
        #pragma unroll
        for (int t = 0; t < 2; ++t) {
            int idx = tid + t * 256;
            int row = idx >> 2, ch = idx & 3;
            uint32_t so = (uint32_t)row * 64 + (uint32_t)((ch ^ ((row >> 1) & 3)) << 4);
            CP_ASYNC16(st + so, Ah + (size_t)(bm + row) * K + kc + ch * 8);
        }
        #pragma unroll
        for (int t = 0; t < 2; ++t) {
            int idx = tid + t * 256;
            int row = idx >> 4, c = idx & 15;
            uint32_t so = (uint32_t)row * 256 + (uint32_t)((c ^ (row & 15)) << 4);
            CP_ASYNC16(st + G_PART + so, Bh + (size_t)(kc + row) * N + bn + c * 8);
        }
        CP_COMMIT();
    };

    load_stage(0, 0);
    load_stage(1, 1);

    int slot = 0, slot2 = 2;
    for (int j = 0; j < nst; ++j) {
        if (j + 1 < nst) { CP_WAIT(1); }
        else             { CP_WAIT(0); }
        __syncthreads();
        if (j + 2 < nst) load_stage(j + 2, slot2);

        const uint32_t st = sb + (uint32_t)slot * G_STAGE;
        #pragma unroll
        for (int ks = 0; ks < 2; ++ks) {
            uint32_t ah[4][4], bh[2][4];   // bh[p] = frags for n-groups 2p, 2p+1
            #pragma unroll
            for (int mt = 0; mt < 4; ++mt) {
                uint32_t ao = (uint32_t)(rA + mt * 16) * 64
                            + (uint32_t)(((ks * 2 + kA) ^ swz) << 4);
                LDSM_X4(ah[mt], st + ao);
            }
            {
                int krow = ks * 16 + kB16;
                uint32_t brow = st + G_PART + (uint32_t)krow * 256;
                #pragma unroll
                for (int p = 0; p < 2; ++p) {
                    uint32_t cb = (uint32_t)(warp_n * 4 + p * 2 + nfh);
                    LDSM_X4T(bh[p], brow + (((cb ^ (krow & 15)) & 15) << 4));
                }
            }
            #pragma unroll
            for (int mt = 0; mt < 4; ++mt)
                #pragma unroll
                for (int nt = 0; nt < 4; ++nt)
                    MMAF16(acc[mt][nt], ah[mt],
                           bh[nt >> 1][(nt & 1) * 2], bh[nt >> 1][(nt & 1) * 2 + 1]);
        }
        slot  = (slot  == 2) ? 0 : slot  + 1;
        slot2 = (slot2 == 2) ? 0 : slot2 + 1;
    }

    // epilogue
    #pragma unroll
    for (int mt = 0; mt < 4; ++mt)
        #pragma unroll
        for (int nt = 0; nt < 4; ++nt) {
            int row0 = bm + warp_m * 64 + mt * 16 + (lane >> 2);
            int col  = bn + warp_n * 32 + nt * 8 + (lane & 3) * 2;
            float b0 = bias[col], b1 = bias[col + 1];
            float v[4];
            v[0] = acc[mt][nt][0] + b0;
            v[1] = acc[mt][nt][1] + b1;
            v[2] = acc[mt][nt][2] + b0;
            v[3] = acc[mt][nt][3] + b1;
            if (act) {
                #pragma unroll
                for (int r = 0; r < 4; ++r)
                    v[r] = 0.5f * v[r] * (1.f + erff(v[r] * 0.70710678118654752f));
            }
            if (Cf) {
                *(float2*)&Cf[(size_t)row0 * N + col]       = make_float2(v[0], v[1]);
                *(float2*)&Cf[(size_t)(row0 + 8) * N + col] = make_float2(v[2], v[3]);
            } else {
                uint32_t p0 = pack_h2f(v[0], v[1]);
                uint32_t p1 = pack_h2f(v[2], v[3]);
                *(uint32_t*)&Ch[(size_t)row0 * N + col]       = p0;
                *(uint32_t*)&Ch[(size_t)(row0 + 8) * N + col] = p1;
            }
        }
}

// ---------------- tensor-core attention (R15 structure, x4 loads) -------------
#define SCW(hh, b, p) ((hh) * 290 + (b) * 18 + (p))
#define AT_STG 65536                 // K (32KB) + V (32KB) per stage
#define ATTN_SMEM (2 * AT_STG + (290 * 16 + 288) * 4)

__global__ __launch_bounds__(512, 1) void attn_kernel(
    const __half* __restrict__ Ph, __half* __restrict__ Oh)
{
    extern __shared__ char smem[];
    const uint32_t sb = smem_u32(smem);
    float* sc   = (float*)(smem + 2 * AT_STG);
    float* invb = sc + 290 * 16;          // [16][18] padded 1/sum per (b, b')

    const int tid = threadIdx.x, lane = tid & 31, h = tid >> 5;
    const int a = blockIdx.x, n = blockIdx.y;
    const int lr = lane >> 2, lc = lane & 3;

    // ---- stage Q into stage-0 area, extract fragments ----
    {
        #pragma unroll
        for (int t = 0; t < 4; ++t) {
            int f = tid + t * 512;
            int hh = f >> 7, bp = (f >> 3) & 15, c = f & 7;
            uint32_t dst = (uint32_t)hh * 2048 + bp * 128 + ((c ^ (bp & 7)) << 4);
            size_t src = (size_t)(n * 1024 + hh * 64 + a) * 3072 + bp * 64 + c * 8;
            CP_ASYNC16(sb + dst, Ph + src);
        }
        CP_COMMIT(); CP_WAIT(0); __syncthreads();
    }
    uint32_t qh[4][4];
    {
        int b = lane & 15, cs = lane >> 4;
        #pragma unroll
        for (int ks = 0; ks < 4; ++ks) {
            uint32_t ad = (uint32_t)h * 2048 + b * 128
                        + (((ks * 2 + cs) ^ (b & 7)) << 4);
            LDSM_X4(qh[ks], sb + ad);
        }
    }
    __syncthreads();   // everyone done reading Q before KV overwrites stage 0

    auto stageKV = [&](int ap, int s) {
        uint32_t base = sb + (uint32_t)s * AT_STG;
        #pragma unroll
        for (int t = 0; t < 4; ++t) {
            int f = tid + t * 512;
            int hh = f >> 7, bp = (f >> 3) & 15, c = f & 7;
            uint32_t dst = (uint32_t)hh * 2048 + bp * 128 + ((c ^ (bp & 7)) << 4);
            size_t row = (size_t)(n * 1024 + hh * 64 + ap) * 3072;
            CP_ASYNC16(base + dst,         Ph + row + 1024 + bp * 64 + c * 8);
            CP_ASYNC16(base + 32768 + dst, Ph + row + 2048 + bp * 64 + c * 8);
        }
        CP_COMMIT();
    };

    float o[8][4];
    #pragma unroll
    for (int nt = 0; nt < 8; ++nt)
        #pragma unroll
        for (int r = 0; r < 4; ++r) o[nt][r] = 0.f;

    stageKV(0, 0);
    for (int ap = 0; ap < 64; ++ap) {
        const int s = ap & 1;
        CP_WAIT(0);
        __syncthreads();   // syncA

        const uint32_t kb = sb + (uint32_t)s * AT_STG;
        const uint32_t vb = kb + 32768;

        // ---- scores: S = Q K^T (x4: lanes 16-31 take b'-rows 8-15) ----
        float sv[2][4];
        #pragma unroll
        for (int nt = 0; nt < 2; ++nt)
            #pragma unroll
            for (int r = 0; r < 4; ++r) sv[nt][r] = 0.f;
        {
            // m0: b'0-7 k0-7 | m1: b'0-7 k8-15 | m2: b'8-15 k0-7 | m3: b'8-15 k8-15
            int row = ((lane >> 4) & 1) * 8 + (lane & 7);
            int khalf = (lane >> 3) & 1;
            #pragma unroll
            for (int ks = 0; ks < 4; ++ks) {
                uint32_t ad = (uint32_t)h * 2048 + row * 128
                            + (((ks * 2 + khalf) ^ (row & 7)) << 4);
                uint32_t k4[4];
                LDSM_X4(k4, kb + ad);
                MMAF16(sv[0], qh[ks], k4[0], k4[1]);
                MMAF16(sv[1], qh[ks], k4[2], k4[3]);
            }
        }
        #pragma unroll
        for (int nt = 0; nt < 2; ++nt) {
            int c0 = nt * 8 + 2 * lc;
            sc[SCW(h, lr,     c0)]     = sv[nt][0] * 0.03125f;
            sc[SCW(h, lr,     c0 + 1)] = sv[nt][1] * 0.03125f;
            sc[SCW(h, lr + 8, c0)]     = sv[nt][2] * 0.03125f;
            sc[SCW(h, lr + 8, c0 + 1)] = sv[nt][3] * 0.03125f;
        }
        __syncthreads();   // syncB

        if (ap + 1 < 64) stageKV(ap + 1, s ^ 1);

        // ---- 1-pass head-softmax: raw exp + 1/sum ----
        if (tid < 256) {
            const int pb = tid >> 4, pbp = tid & 15;
            float ssum = 0.f;
            #pragma unroll
            for (int hh = 0; hh < 16; ++hh) {
                float e = __expf(sc[SCW(hh, pb, pbp)]);
                ssum += e;
                sc[SCW(hh, pb, pbp)] = e;
            }
            invb[pb * 18 + pbp] = 1.f / ssum;
        }
        __syncthreads();   // syncC

        // ---- W fragments: fp16(e * inv) ----
        uint32_t awh[4];
        {
            float i00 = invb[lr * 18 + 2 * lc],       i01 = invb[lr * 18 + 2 * lc + 1];
            float i10 = invb[(lr + 8) * 18 + 2 * lc], i11 = invb[(lr + 8) * 18 + 2 * lc + 1];
            float i02 = invb[lr * 18 + 2 * lc + 8],       i03 = invb[lr * 18 + 2 * lc + 9];
            float i12 = invb[(lr + 8) * 18 + 2 * lc + 8], i13 = invb[(lr + 8) * 18 + 2 * lc + 9];
            awh[0] = pack_h2f(sc[SCW(h, lr,     2 * lc)] * i00,
                              sc[SCW(h, lr,     2 * lc + 1)] * i01);
            awh[1] = pack_h2f(sc[SCW(h, lr + 8, 2 * lc)] * i10,
                              sc[SCW(h, lr + 8, 2 * lc + 1)] * i11);
            awh[2] = pack_h2f(sc[SCW(h, lr,     2 * lc + 8)] * i02,
                              sc[SCW(h, lr,     2 * lc + 9)] * i03);
            awh[3] = pack_h2f(sc[SCW(h, lr + 8, 2 * lc + 8)] * i12,
                              sc[SCW(h, lr + 8, 2 * lc + 9)] * i13);
        }

        // ---- AV: O += W V (x4T: lanes 16-31 take chunk nt+1) ----
        {
            int bp = lane & 15;
            int ch = lane >> 4;       // 0 -> m0,m1 (chunk nt); 1 -> m2,m3 (nt+1)
            #pragma unroll
            for (int nt = 0; nt < 8; nt += 2) {
                uint32_t ad = (uint32_t)h * 2048 + bp * 128
                            + ((((nt + ch) ^ (bp & 7)) & 7) << 4);
                uint32_t v4[4];
                LDSM_X4T(v4, vb + ad);
                MMAF16(o[nt],     awh, v4[0], v4[1]);
                MMAF16(o[nt + 1], awh, v4[2], v4[3]);
            }
        }
    }

    // ---- write O as fp16 ----
    const size_t orow = (size_t)(n * 1024 + h * 64 + a) * 1024;
    #pragma unroll
    for (int nt = 0; nt < 8; ++nt) {
        int c0 = nt * 8 + 2 * lc;
        uint32_t p0 = pack_h2f(o[nt][0], o[nt][1]);
        uint32_t p1 = pack_h2f(o[nt][2], o[nt][3]);
        *(uint32_t*)(Oh + orow + lr * 64 + c0)       = p0;
        *(uint32_t*)(Oh + orow + (lr + 8) * 64 + c0) = p1;
    }
}

// ---------------- fused residual + LayerNorm (+ optional fp16 emit) ----------
__global__ __launch_bounds__(256) void ln_kernel(
    const float* __restrict__ A, const float* __restrict__ R,
    const float* __restrict__ g, const float* __restrict__ bta,
    float* __restrict__ out, __half* __restrict__ Xh)
{
    __shared__ float red[16];
    const int row = blockIdx.x;
    const int tid = threadIdx.x;

    float4 v = ((const float4*)(A + (size_t)row * 1024))[tid];
    float4 r = ((const float4*)(R + (size_t)row * 1024))[tid];
    v.x += r.x; v.y += r.y; v.z += r.z; v.w += r.w;

    float s  = v.x + v.y + v.z + v.w;
    float sq = v.x * v.x + v.y * v.y + v.z * v.z + v.w * v.w;
    #pragma unroll
    for (int o = 16; o > 0; o >>= 1) {
        s  += __shfl_xor_sync(0xffffffffu, s,  o);
        sq += __shfl_xor_sync(0xffffffffu, sq, o);
    }
    if ((tid & 31) == 0) { red[tid >> 5] = s; red[8 + (tid >> 5)] = sq; }
    __syncthreads();
    float S = 0.f, SQ = 0.f;
    #pragma unroll
    for (int w = 0; w < 8; ++w) { S += red[w]; SQ += red[8 + w]; }

    const float mean = S * (1.f / 1024.f);
    const float var  = SQ * (1.f / 1024.f) - mean * mean;
    const float rstd = rsqrtf(var + 1e-5f);

    float4 gv = ((const float4*)g)[tid];
    float4 bv = ((const float4*)bta)[tid];
    float4 o;
    o.x = (v.x - mean) * rstd * gv.x + bv.x;
    o.y = (v.y - mean) * rstd * gv.y + bv.y;
    o.z = (v.z - mean) * rstd * gv.z + bv.z;
    o.w = (v.w - mean) * rstd * gv.w + bv.w;
    ((float4*)(out + (size_t)row * 1024))[tid] = o;

    if (Xh) {
        size_t oo = (size_t)row * 1024 + tid * 4;
        *(__half2*)(Xh + oo)     = __halves2half2(__float2half_rn(o.x), __float2half_rn(o.y));
        *(__half2*)(Xh + oo + 2) = __halves2half2(__float2half_rn(o.z), __float2half_rn(o.w));
    }
}

// ---------------- launch ------------------------------------------------------
extern "C" void kernel_launch(void* const* d_in, const int* in_sizes, int n_in,
                              void* d_out, int out_size)
{
    const float* x  = (const float*)d_in[0];
    const float* Wq = (const float*)d_in[1];
    const float* bq = (const float*)d_in[2];
    const float* Wk = (const float*)d_in[3];
    const float* bk = (const float*)d_in[4];
    const float* Wv = (const float*)d_in[5];
    const float* bv = (const float*)d_in[6];
    const float* Wo = (const float*)d_in[7];
    const float* bo = (const float*)d_in[8];
    const float* g1 = (const float*)d_in[9];
    const float* b1 = (const float*)d_in[10];
    const float* W1 = (const float*)d_in[11];
    const float* c1 = (const float*)d_in[12];
    const float* W2 = (const float*)d_in[13];
    const float* c2 = (const float*)d_in[14];
    const float* g2 = (const float*)d_in[15];
    const float* b2 = (const float*)d_in[16];
    float* out = (float*)d_out;

    float *pX1, *pF, *pbqkv;
    __half *pAh, *pHh, *pBq, *pBo, *pB1, *pB2;
    cudaGetSymbolAddress((void**)&pX1,  g_X1);
    cudaGetSymbolAddress((void**)&pF,   g_F);
    cudaGetSymbolAddress((void**)&pbqkv,g_bqkv);
    cudaGetSymbolAddress((void**)&pAh,  g_Ah);
    cudaGetSymbolAddress((void**)&pHh,  g_Hh);
    cudaGetSymbolAddress((void**)&pBq,  g_Bq);
    cudaGetSymbolAddress((void**)&pBo,  g_Bo);
    cudaGetSymbolAddress((void**)&pB1,  g_B1);
    cudaGetSymbolAddress((void**)&pB2,  g_B2);

    cudaFuncSetAttribute(attn_kernel, cudaFuncAttributeMaxDynamicSharedMemorySize, ATTN_SMEM);
    cudaFuncSetAttribute(gemm_tc_kernel, cudaFuncAttributeMaxDynamicSharedMemorySize, G_SMEM);

    dim3 blk(256);
    const int n4_1 = NTOK * HID / 4;
    dim3 gs1((n4_1 + 255) / 256);
    dim3 ggqkv(3 * HID / 128, NTOK / 128);
    dim3 gg1(HID / 128, NTOK / 128);
    dim3 gg4(4 * HID / 128, NTOK / 128);

    // ---- conversions: x + all weights (streaming, no transpose) ----
    cvt_kernel<<<gs1, blk>>>(x, pAh, n4_1);
    prep_kernel<<<(3146496 + 255) / 256, blk>>>(Wq, Wk, Wv, Wo, W1, W2,
                                                bq, bk, bv,
                                                pBq, pBo, pB1, pB2, pbqkv);

    // ---- QKV GEMM (N=3072) -> fp16 ----
    gemm_tc_kernel<<<ggqkv, blk, G_SMEM>>>(pAh, pBq, pbqkv,
                                           nullptr, pHh,
                                           NTOK, 3 * HID, HID, 0);

    // ---- tensor-core attention; emits O fp16 ----
    attn_kernel<<<dim3(64, 4), 512, ATTN_SMEM>>>(pHh, pAh);

    // ---- output projection, residual + LN1 (emits X1 fp32 + fp16) ----
    gemm_tc_kernel<<<gg1, blk, G_SMEM>>>(pAh, pBo, bo,
                                         pF, nullptr,
                                         NTOK, HID, HID, 0);
    ln_kernel<<<NTOK, blk>>>(pF, x, g1, b1, pX1, pAh);

    // ---- FFN ----
    gemm_tc_kernel<<<gg4, blk, G_SMEM>>>(pAh, pB1, c1,
                                         nullptr, pHh,
                                         NTOK, 4 * HID, HID, 1);
    gemm_tc_kernel<<<gg1, blk, G_SMEM>>>(pHh, pB2, c2,
                                         pF, nullptr,
                                         NTOK, HID, 4 * HID, 0);

    // ---- residual + LN2 -> output ----
    ln_kernel<<<NTOK, blk>>>(pF, pX1, g2, b2, out, nullptr);
}